// round 15
// baseline (speedup 1.0000x reference)
#include <cuda_runtime.h>
#include <math.h>

#define NN 100000
#define EE 1600000
#define BBATCH 64

typedef unsigned long long u64t;

// ---------------- scratch (static device arrays; no allocation) ----------------
__device__ float    g_xl[NN * 96];      // x @ W_l + b_l
__device__ float    g_xr[NN * 96];      // x @ W_r + b_r
__device__ float    g_P [NN * 32];      // x @ W_edge[:64] + b_edge
__device__ float    g_ex[EE * 3];       // exp(logit)  (no max subtraction needed)
__device__ float    g_den[NN * 3];      // softmax denominators
__device__ float    g_gat[NN * 96];     // aggregated messages
__device__ float    g_bsum[BBATCH * 32];
__device__ int      g_bcnt[BBATCH];

// ---------------- packed f32x2 helpers ----------------
__device__ __forceinline__ void fma2(u64t& d, u64t a, u64t b) {
    asm("fma.rn.f32x2 %0, %1, %2, %0;" : "+l"(d) : "l"(a), "l"(b));
}
__device__ __forceinline__ u64t pk(float a) {
    u64t r;
    asm("mov.b64 %0, {%1, %1};" : "=l"(r) : "f"(a));
    return r;
}
__device__ __forceinline__ void upk(u64t v, float& lo, float& hi) {
    asm("mov.b64 {%0, %1}, %2;" : "=f"(lo), "=f"(hi) : "l"(v));
}

// ======================= Kernel A: node transforms xl, xr, P =======================
__global__ void __launch_bounds__(128) nodeTransformK(
    const float* __restrict__ x,
    const float* __restrict__ Wl, const float* __restrict__ bl,
    const float* __restrict__ Wr, const float* __restrict__ br,
    const float* __restrict__ Wedge, const float* __restrict__ bedge)
{
    extern __shared__ float sm[];
    float* sWl = sm;               // 64*96
    float* sWr = sWl + 6144;       // 64*96
    float* sWp = sWr + 6144;       // 64*32
    float* sX  = sWp + 2048;       // 64*66
    float* sbl = sX + 64 * 66;     // 96
    float* sbr = sbl + 96;         // 96
    float* sbp = sbr + 96;         // 32

    int t = threadIdx.x;
    for (int i = t; i < 6144; i += 128) { sWl[i] = Wl[i]; sWr[i] = Wr[i]; }
    for (int i = t; i < 2048; i += 128) sWp[i] = Wedge[i];
    for (int i = t; i < 96; i += 128)   { sbl[i] = bl[i]; sbr[i] = br[i]; }
    if (t < 32) sbp[t] = bedge[t];

    int n0 = blockIdx.x * 64;
    for (int i = t; i < 4096; i += 128) {
        int r = i >> 6, c = i & 63;
        int n = n0 + r;
        sX[r * 66 + c] = (n < NN) ? x[(size_t)n * 64 + c] : 0.f;
    }
    __syncthreads();

    int er = t & 15, oc = t >> 4;
    int rb0 = er * 66, rb1 = rb0 + 16 * 66, rb2 = rb1 + 16 * 66, rb3 = rb2 + 16 * 66;

    #pragma unroll
    for (int pass = 0; pass < 2; pass++) {
        const float* W   = pass ? sWr : sWl;
        const float* bia = pass ? sbr : sbl;
        float* dst       = pass ? g_xr : g_xl;

        u64t acc[4][6];
        #pragma unroll
        for (int i = 0; i < 4; i++)
            #pragma unroll
            for (int j = 0; j < 6; j++) acc[i][j] = 0ull;

        #pragma unroll 4
        for (int k = 0; k < 64; k++) {
            u64t a0 = pk(sX[rb0 + k]), a1 = pk(sX[rb1 + k]);
            u64t a2 = pk(sX[rb2 + k]), a3 = pk(sX[rb3 + k]);
            const u64t* bp = (const u64t*)(W + k * 96 + oc * 12);
            u64t b0 = bp[0], b1 = bp[1], b2 = bp[2], b3 = bp[3], b4 = bp[4], b5 = bp[5];
            fma2(acc[0][0], a0, b0); fma2(acc[0][1], a0, b1); fma2(acc[0][2], a0, b2);
            fma2(acc[0][3], a0, b3); fma2(acc[0][4], a0, b4); fma2(acc[0][5], a0, b5);
            fma2(acc[1][0], a1, b0); fma2(acc[1][1], a1, b1); fma2(acc[1][2], a1, b2);
            fma2(acc[1][3], a1, b3); fma2(acc[1][4], a1, b4); fma2(acc[1][5], a1, b5);
            fma2(acc[2][0], a2, b0); fma2(acc[2][1], a2, b1); fma2(acc[2][2], a2, b2);
            fma2(acc[2][3], a2, b3); fma2(acc[2][4], a2, b4); fma2(acc[2][5], a2, b5);
            fma2(acc[3][0], a3, b0); fma2(acc[3][1], a3, b1); fma2(acc[3][2], a3, b2);
            fma2(acc[3][3], a3, b3); fma2(acc[3][4], a3, b4); fma2(acc[3][5], a3, b5);
        }
        #pragma unroll
        for (int i = 0; i < 4; i++) {
            int n = n0 + er + 16 * i;
            if (n < NN) {
                float o[12];
                #pragma unroll
                for (int j = 0; j < 6; j++) upk(acc[i][j], o[2 * j], o[2 * j + 1]);
                #pragma unroll
                for (int j = 0; j < 12; j++) o[j] += bia[oc * 12 + j];
                float4* op = (float4*)(dst + (size_t)n * 96 + oc * 12);
                op[0] = make_float4(o[0], o[1], o[2], o[3]);
                op[1] = make_float4(o[4], o[5], o[6], o[7]);
                op[2] = make_float4(o[8], o[9], o[10], o[11]);
            }
        }
    }

    // P pass
    {
        u64t acc[4][2];
        #pragma unroll
        for (int i = 0; i < 4; i++) { acc[i][0] = 0ull; acc[i][1] = 0ull; }
        #pragma unroll 8
        for (int k = 0; k < 64; k++) {
            u64t a0 = pk(sX[rb0 + k]), a1 = pk(sX[rb1 + k]);
            u64t a2 = pk(sX[rb2 + k]), a3 = pk(sX[rb3 + k]);
            const u64t* bp = (const u64t*)(sWp + k * 32 + oc * 4);
            u64t b0 = bp[0], b1 = bp[1];
            fma2(acc[0][0], a0, b0); fma2(acc[0][1], a0, b1);
            fma2(acc[1][0], a1, b0); fma2(acc[1][1], a1, b1);
            fma2(acc[2][0], a2, b0); fma2(acc[2][1], a2, b1);
            fma2(acc[3][0], a3, b0); fma2(acc[3][1], a3, b1);
        }
        #pragma unroll
        for (int i = 0; i < 4; i++) {
            int n = n0 + er + 16 * i;
            if (n < NN) {
                float o0, o1, o2, o3;
                upk(acc[i][0], o0, o1);
                upk(acc[i][1], o2, o3);
                *(float4*)(g_P + (size_t)n * 32 + oc * 4) = make_float4(
                    o0 + sbp[oc * 4 + 0], o1 + sbp[oc * 4 + 1],
                    o2 + sbp[oc * 4 + 2], o3 + sbp[oc * 4 + 3]);
            }
        }
    }
}

// ======================= Kernel B: fused edge kernel (128 thr, 4 rows/thread, occ=7) ========
__global__ void __launch_bounds__(128, 7) edgeK(
    const float* __restrict__ ea,
    const float* __restrict__ Wedge,
    const float* __restrict__ We, const float* __restrict__ att,
    const int* __restrict__ srcp, const int* __restrict__ dstp,
    float* __restrict__ e_out)
{
    extern __shared__ float sm[];
    float* sWb  = sm;                 // 32*32  (W_edge rows 64..95)
    float* sW2  = sWb + 1024;         // 32*96  (W_e)
    float* sEA  = sW2 + 3072;         // 64*34
    float* sE   = sEA + 64 * 34;      // 64*34
    int*   sSrc = (int*)(sE + 64 * 34); // 64
    int*   sDst = sSrc + 64;          // 64

    int t = threadIdx.x;
    for (int i = t; i < 1024; i += 128) sWb[i] = Wedge[2048 + i];
    for (int i = t; i < 3072; i += 128) sW2[i] = We[i];

    int oc = t & 7, er = t >> 3;
    int c0 = oc * 12;
    int oc4 = oc * 4;

    float attv[12];
    #pragma unroll
    for (int j = 0; j < 12; j++) attv[j] = att[c0 + j];

    int hA = c0 >> 5;
    int hB = (c0 + 11) >> 5;
    int split = (hB > hA) ? (hB * 32 - c0) : 12;

    int rb0 = er * 34, rb1 = rb0 + 16 * 34, rb2 = rb1 + 16 * 34, rb3 = rb2 + 16 * 34;

    __syncthreads();

    for (int tile = blockIdx.x; tile < EE / 64; tile += gridDim.x) {
        int e0 = tile * 64;
        if (t < 64) { sSrc[t] = srcp[e0 + t]; sDst[t] = dstp[e0 + t]; }
        for (int i = t; i < 512; i += 128) {
            int r = i >> 3, c4 = i & 7;
            float4 v = *(const float4*)(ea + (size_t)(e0 + r) * 32 + c4 * 4);
            int b = r * 34 + c4 * 4;
            sEA[b] = v.x; sEA[b + 1] = v.y; sEA[b + 2] = v.z; sEA[b + 3] = v.w;
        }
        __syncthreads();

        // early P gather, hidden under GEMM1 k-loop
        float4 pP[4];
        #pragma unroll
        for (int i = 0; i < 4; i++)
            pP[i] = *(const float4*)(g_P + (size_t)sSrc[er + 16 * i] * 32 + oc4);

        // GEMM1: tmp = ea @ Wb, e = relu(tmp + P[src])
        {
            u64t acc[4][2];
            #pragma unroll
            for (int i = 0; i < 4; i++) { acc[i][0] = 0ull; acc[i][1] = 0ull; }
            #pragma unroll 8
            for (int k = 0; k < 32; k++) {
                u64t a0 = pk(sEA[rb0 + k]), a1 = pk(sEA[rb1 + k]);
                u64t a2 = pk(sEA[rb2 + k]), a3 = pk(sEA[rb3 + k]);
                const u64t* bp = (const u64t*)(sWb + k * 32 + oc4);
                u64t b0 = bp[0], b1 = bp[1];
                fma2(acc[0][0], a0, b0); fma2(acc[0][1], a0, b1);
                fma2(acc[1][0], a1, b0); fma2(acc[1][1], a1, b1);
                fma2(acc[2][0], a2, b0); fma2(acc[2][1], a2, b1);
                fma2(acc[3][0], a3, b0); fma2(acc[3][1], a3, b1);
            }
            #pragma unroll
            for (int i = 0; i < 4; i++) {
                int row = er + 16 * i;
                float o0, o1, o2, o3;
                upk(acc[i][0], o0, o1);
                upk(acc[i][1], o2, o3);
                float v0 = fmaxf(o0 + pP[i].x, 0.f);
                float v1 = fmaxf(o1 + pP[i].y, 0.f);
                float v2 = fmaxf(o2 + pP[i].z, 0.f);
                float v3 = fmaxf(o3 + pP[i].w, 0.f);
                *(float4*)(e_out + (size_t)(e0 + row) * 32 + oc4) =
                    make_float4(v0, v1, v2, v3);
                int b = row * 34 + oc4;
                sE[b] = v0; sE[b + 1] = v1; sE[b + 2] = v2; sE[b + 3] = v3;
            }
        }
        __syncthreads();

        // GEMM2: M1 = e @ W_e, fused logits -> exp -> den atomics
        {
            u64t acc2[4][6];
            #pragma unroll
            for (int i = 0; i < 4; i++)
                #pragma unroll
                for (int j = 0; j < 6; j++) acc2[i][j] = 0ull;
            #pragma unroll 8
            for (int k = 0; k < 32; k++) {
                u64t a0 = pk(sE[rb0 + k]), a1 = pk(sE[rb1 + k]);
                u64t a2 = pk(sE[rb2 + k]), a3 = pk(sE[rb3 + k]);
                const u64t* bp = (const u64t*)(sW2 + k * 96 + c0);
                u64t b0 = bp[0], b1 = bp[1], b2 = bp[2], b3 = bp[3], b4 = bp[4], b5 = bp[5];
                fma2(acc2[0][0], a0, b0); fma2(acc2[0][1], a0, b1); fma2(acc2[0][2], a0, b2);
                fma2(acc2[0][3], a0, b3); fma2(acc2[0][4], a0, b4); fma2(acc2[0][5], a0, b5);
                fma2(acc2[1][0], a1, b0); fma2(acc2[1][1], a1, b1); fma2(acc2[1][2], a1, b2);
                fma2(acc2[1][3], a1, b3); fma2(acc2[1][4], a1, b4); fma2(acc2[1][5], a1, b5);
                fma2(acc2[2][0], a2, b0); fma2(acc2[2][1], a2, b1); fma2(acc2[2][2], a2, b2);
                fma2(acc2[2][3], a2, b3); fma2(acc2[2][4], a2, b4); fma2(acc2[2][5], a2, b5);
                fma2(acc2[3][0], a3, b0); fma2(acc2[3][1], a3, b1); fma2(acc2[3][2], a3, b2);
                fma2(acc2[3][3], a3, b3); fma2(acc2[3][4], a3, b4); fma2(acc2[3][5], a3, b5);
            }

            // pipelined epilogue: load row i+1's xl/xr while reducing row i
            float4 xa[3], xb[3], nxa[3], nxb[3];
            {
                int s0 = sSrc[er], d0 = sDst[er];
                const float4* xlp = (const float4*)(g_xl + (size_t)s0 * 96 + c0);
                const float4* xrp = (const float4*)(g_xr + (size_t)d0 * 96 + c0);
                #pragma unroll
                for (int q = 0; q < 3; q++) { xa[q] = xlp[q]; xb[q] = xrp[q]; }
            }
            #pragma unroll
            for (int i = 0; i < 4; i++) {
                int row = er + 16 * i;
                int d = sDst[row];
                if (i < 3) {
                    int s1 = sSrc[row + 16], d1 = sDst[row + 16];
                    const float4* xlp = (const float4*)(g_xl + (size_t)s1 * 96 + c0);
                    const float4* xrp = (const float4*)(g_xr + (size_t)d1 * 96 + c0);
                    #pragma unroll
                    for (int q = 0; q < 3; q++) { nxa[q] = xlp[q]; nxb[q] = xrp[q]; }
                }
                float m1v[12];
                #pragma unroll
                for (int j = 0; j < 6; j++) upk(acc2[i][j], m1v[2 * j], m1v[2 * j + 1]);
                float pA = 0.f, pB = 0.f;
                #pragma unroll
                for (int q = 0; q < 3; q++) {
                    float mm[4];
                    mm[0] = m1v[q * 4 + 0] + xa[q].x + xb[q].x;
                    mm[1] = m1v[q * 4 + 1] + xa[q].y + xb[q].y;
                    mm[2] = m1v[q * 4 + 2] + xa[q].z + xb[q].z;
                    mm[3] = m1v[q * 4 + 3] + xa[q].w + xb[q].w;
                    #pragma unroll
                    for (int jj = 0; jj < 4; jj++) {
                        int j = q * 4 + jj;
                        float m = mm[jj];
                        m = (m > 0.f) ? m : 0.2f * m;
                        float v = m * attv[j];
                        if (j < split) pA += v; else pB += v;
                    }
                }
                #pragma unroll
                for (int h = 0; h < 3; h++) {
                    float v = (hA == h ? pA : 0.f) + ((hB == h && hB != hA) ? pB : 0.f);
                    v += __shfl_xor_sync(0xffffffffu, v, 1);
                    v += __shfl_xor_sync(0xffffffffu, v, 2);
                    v += __shfl_xor_sync(0xffffffffu, v, 4);
                    if (oc == h) {
                        float ex = __expf(v);
                        g_ex[(size_t)(e0 + row) * 3 + h] = ex;
                        atomicAdd(&g_den[d * 3 + h], ex);
                    }
                }
                #pragma unroll
                for (int q = 0; q < 3; q++) { xa[q] = nxa[q]; xb[q] = nxb[q]; }
            }
        }
        __syncthreads();
    }
}

// ======================= Kernel D: scatter with fused alpha (8 edges/warp) =======================
__global__ void __launch_bounds__(256) scatterK(const int* __restrict__ srcp,
                                                const int* __restrict__ dstp)
{
    int warp = blockIdx.x * 8 + (threadIdx.x >> 5);
    int lane = threadIdx.x & 31;
    int e0 = warp * 8;

    int s_own = 0, d_own = 0;
    if (lane < 8) { s_own = srcp[e0 + lane]; d_own = dstp[e0 + lane]; }
    float a_own = 0.f;
    if (lane < 24) {
        int es = lane / 3, h = lane - es * 3;
        int d = dstp[e0 + es];
        a_own = g_ex[(size_t)(e0 + es) * 3 + h] / g_den[d * 3 + h];
    }

    #pragma unroll
    for (int i = 0; i < 6; i++) {
        int idx = lane + 32 * i;        // 0..191
        int es = idx / 24;              // 0..7
        int chunk = idx - es * 24;      // 0..23
        int h = chunk >> 3;
        int s = __shfl_sync(0xffffffffu, s_own, es);
        int d = __shfl_sync(0xffffffffu, d_own, es);
        float al = __shfl_sync(0xffffffffu, a_own, es * 3 + h);
        float4 xv = *(const float4*)(g_xl + (size_t)s * 96 + chunk * 4);
        float* gp = g_gat + (size_t)d * 96 + chunk * 4;
        asm volatile("red.global.add.v4.f32 [%0], {%1,%2,%3,%4};"
                     :: "l"(gp), "f"(al * xv.x), "f"(al * xv.y),
                        "f"(al * xv.z), "f"(al * xv.w)
                     : "memory");
    }
}

// ======================= Kernel E: node_mlp_2 — 2 threads/node, 16 outputs each ====
__global__ void __launch_bounds__(256, 5) node2K(
    const float* __restrict__ glob, const int* __restrict__ batch,
    const float* __restrict__ Wn2, const float* __restrict__ bn2,
    const float* __restrict__ bias_gat, float* __restrict__ xnew)
{
    __shared__ float sW[4096];   // 128 x 32
    __shared__ float sBg[96];
    __shared__ float sBn[32];

    int t = threadIdx.x;
    for (int i = t; i < 4096; i += 256) sW[i] = Wn2[i];
    if (t < 96) sBg[t] = bias_gat[t];
    else if (t < 128) sBn[t - 96] = bn2[t - 96];
    __syncthreads();

    int n = blockIdx.x * 128 + (t >> 1);
    int half = t & 1;                 // 0: cols 0..15, 1: cols 16..31
    bool valid = (n < NN);
    int nn = valid ? n : (NN - 1);
    int bb = batch[nn];

    u64t acc[8];
    #pragma unroll
    for (int q = 0; q < 8; q++) acc[q] = 0ull;

    const float4* gr = (const float4*)(g_gat + (size_t)nn * 96);
    const float4* gl = (const float4*)(glob + bb * 32);
    int hofs = half * 8;              // u64 offset into each W row

    // k = 0..95: gat row + bias_gat
    #pragma unroll
    for (int c4 = 0; c4 < 24; c4++) {
        float4 v = gr[c4];
        float a0 = v.x + sBg[c4 * 4 + 0];
        float a1 = v.y + sBg[c4 * 4 + 1];
        float a2 = v.z + sBg[c4 * 4 + 2];
        float a3 = v.w + sBg[c4 * 4 + 3];
        const u64t* b0 = (const u64t*)(sW + (c4 * 4 + 0) * 32) + hofs;
        const u64t* b1 = (const u64t*)(sW + (c4 * 4 + 1) * 32) + hofs;
        const u64t* b2 = (const u64t*)(sW + (c4 * 4 + 2) * 32) + hofs;
        const u64t* b3 = (const u64t*)(sW + (c4 * 4 + 3) * 32) + hofs;
        u64t p0 = pk(a0), p1 = pk(a1), p2 = pk(a2), p3 = pk(a3);
        #pragma unroll
        for (int q = 0; q < 8; q++) {
            fma2(acc[q], p0, b0[q]);
            fma2(acc[q], p1, b1[q]);
            fma2(acc[q], p2, b2[q]);
            fma2(acc[q], p3, b3[q]);
        }
    }
    // k = 96..127: glob row
    #pragma unroll
    for (int c4 = 0; c4 < 8; c4++) {
        float4 v = gl[c4];
        const u64t* b0 = (const u64t*)(sW + (96 + c4 * 4 + 0) * 32) + hofs;
        const u64t* b1 = (const u64t*)(sW + (96 + c4 * 4 + 1) * 32) + hofs;
        const u64t* b2 = (const u64t*)(sW + (96 + c4 * 4 + 2) * 32) + hofs;
        const u64t* b3 = (const u64t*)(sW + (96 + c4 * 4 + 3) * 32) + hofs;
        u64t p0 = pk(v.x), p1 = pk(v.y), p2 = pk(v.z), p3 = pk(v.w);
        #pragma unroll
        for (int q = 0; q < 8; q++) {
            fma2(acc[q], p0, b0[q]);
            fma2(acc[q], p1, b1[q]);
            fma2(acc[q], p2, b2[q]);
            fma2(acc[q], p3, b3[q]);
        }
    }

    if (valid) {
        if (half == 0) atomicAdd(&g_bcnt[bb], 1);
        float* xp = xnew + (size_t)n * 32 + half * 16;
        const float* bn = sBn + half * 16;
        #pragma unroll
        for (int q4 = 0; q4 < 4; q4++) {
            float o0, o1, o2, o3;
            upk(acc[q4 * 2], o0, o1);
            upk(acc[q4 * 2 + 1], o2, o3);
            o0 = fmaxf(o0 + bn[q4 * 4 + 0], 0.f);
            o1 = fmaxf(o1 + bn[q4 * 4 + 1], 0.f);
            o2 = fmaxf(o2 + bn[q4 * 4 + 2], 0.f);
            o3 = fmaxf(o3 + bn[q4 * 4 + 3], 0.f);
            *(float4*)(xp + q4 * 4) = make_float4(o0, o1, o2, o3);
            float* bp = g_bsum + bb * 32 + half * 16 + q4 * 4;
            asm volatile("red.global.add.v4.f32 [%0], {%1,%2,%3,%4};"
                         :: "l"(bp), "f"(o0), "f"(o1), "f"(o2), "f"(o3)
                         : "memory");
        }
    }
}

// ======================= Kernel F: global MLP =======================
__global__ void __launch_bounds__(256) globalK(
    const float* __restrict__ glob, const float* __restrict__ Wg,
    const float* __restrict__ bg, float* __restrict__ u_out)
{
    int p = blockIdx.x * 256 + threadIdx.x;
    if (p >= BBATCH * 32) return;
    int b = p >> 5, c = p & 31;
    float acc = bg[c];
    #pragma unroll
    for (int k = 0; k < 32; k++) acc += glob[b * 32 + k] * Wg[k * 32 + c];
    float cnt = fmaxf((float)g_bcnt[b], 1.f);
    float inv = 1.f / cnt;
    #pragma unroll
    for (int k = 0; k < 32; k++) acc += (g_bsum[b * 32 + k] * inv) * Wg[(32 + k) * 32 + c];
    u_out[p] = fmaxf(acc, 0.f);
}

// ======================= launch =======================
extern "C" void kernel_launch(void* const* d_in, const int* in_sizes, int n_in,
                              void* d_out, int out_size)
{
    const float* x        = (const float*)d_in[0];
    const float* ea       = (const float*)d_in[1];
    const float* glob     = (const float*)d_in[2];
    const float* W_edge   = (const float*)d_in[3];
    const float* b_edge   = (const float*)d_in[4];
    const float* W_l      = (const float*)d_in[5];
    const float* b_l      = (const float*)d_in[6];
    const float* W_r      = (const float*)d_in[7];
    const float* b_r      = (const float*)d_in[8];
    const float* W_e      = (const float*)d_in[9];
    const float* att      = (const float*)d_in[10];
    const float* bias_gat = (const float*)d_in[11];
    const float* W_n2     = (const float*)d_in[12];
    const float* b_n2     = (const float*)d_in[13];
    const float* W_g      = (const float*)d_in[14];
    const float* b_g      = (const float*)d_in[15];
    const int* eidx       = (const int*)d_in[16];
    const int* batch      = (const int*)d_in[17];
    const int* srcp = eidx;
    const int* dstp = eidx + EE;

    float* out  = (float*)d_out;
    float* o_x  = out;                       // [N,32]
    float* o_e  = out + (size_t)NN * 32;     // [E,32]
    float* o_u  = o_e + (size_t)EE * 32;     // [B,32]

    const int SMEM_A = (6144 + 6144 + 2048 + 64 * 66 + 96 + 96 + 32) * 4;   // ~75136
    const int SMEM_B = (1024 + 3072 + 64 * 34 + 64 * 34 + 128) * 4;         // ~34304

    cudaFuncSetAttribute(nodeTransformK, cudaFuncAttributeMaxDynamicSharedMemorySize, SMEM_A);
    cudaFuncSetAttribute(edgeK,          cudaFuncAttributeMaxDynamicSharedMemorySize, SMEM_B);

    void* p;
    cudaGetSymbolAddress(&p, g_den);  cudaMemsetAsync(p, 0, (size_t)NN * 3 * 4);
    cudaGetSymbolAddress(&p, g_gat);  cudaMemsetAsync(p, 0, (size_t)NN * 96 * 4);
    cudaGetSymbolAddress(&p, g_bsum); cudaMemsetAsync(p, 0, (size_t)BBATCH * 32 * 4);
    cudaGetSymbolAddress(&p, g_bcnt); cudaMemsetAsync(p, 0, (size_t)BBATCH * 4);

    nodeTransformK<<<(NN + 63) / 64, 128, SMEM_A>>>(x, W_l, b_l, W_r, b_r, W_edge, b_edge);
    edgeK<<<1036, 128, SMEM_B>>>(ea, W_edge, W_e, att, srcp, dstp, o_e);
    scatterK<<<EE / 64, 256>>>(srcp, dstp);
    node2K<<<(NN + 127) / 128, 256>>>(glob, batch, W_n2, b_n2, bias_gat, o_x);
    globalK<<<(BBATCH * 32 + 255) / 256, 256>>>(glob, W_g, b_g, o_u);
}

// round 16
// speedup vs baseline: 1.2915x; 1.2915x over previous
#include <cuda_runtime.h>
#include <math.h>

#define NN 100000
#define EE 1600000
#define BBATCH 64

typedef unsigned long long u64t;

// ---------------- scratch (static device arrays; no allocation) ----------------
__device__ float    g_xl[NN * 96];      // x @ W_l + b_l
__device__ float    g_xr[NN * 96];      // x @ W_r + b_r
__device__ float    g_P [NN * 32];      // x @ W_edge[:64] + b_edge
__device__ float    g_ex[EE * 3];       // exp(logit)  (no max subtraction needed)
__device__ float    g_den[NN * 3];      // softmax denominators
__device__ float    g_gat[NN * 96];     // aggregated messages
__device__ float    g_bsum[BBATCH * 32];
__device__ int      g_bcnt[BBATCH];

// ---------------- packed f32x2 helpers ----------------
__device__ __forceinline__ void fma2(u64t& d, u64t a, u64t b) {
    asm("fma.rn.f32x2 %0, %1, %2, %0;" : "+l"(d) : "l"(a), "l"(b));
}
__device__ __forceinline__ u64t pk(float a) {
    u64t r;
    asm("mov.b64 %0, {%1, %1};" : "=l"(r) : "f"(a));
    return r;
}
__device__ __forceinline__ void upk(u64t v, float& lo, float& hi) {
    asm("mov.b64 {%0, %1}, %2;" : "=f"(lo), "=f"(hi) : "l"(v));
}

// ======================= Kernel A: node transforms xl, xr, P =======================
__global__ void __launch_bounds__(128) nodeTransformK(
    const float* __restrict__ x,
    const float* __restrict__ Wl, const float* __restrict__ bl,
    const float* __restrict__ Wr, const float* __restrict__ br,
    const float* __restrict__ Wedge, const float* __restrict__ bedge)
{
    extern __shared__ float sm[];
    float* sWl = sm;               // 64*96
    float* sWr = sWl + 6144;       // 64*96
    float* sWp = sWr + 6144;       // 64*32
    float* sX  = sWp + 2048;       // 64*66
    float* sbl = sX + 64 * 66;     // 96
    float* sbr = sbl + 96;         // 96
    float* sbp = sbr + 96;         // 32

    int t = threadIdx.x;
    for (int i = t; i < 6144; i += 128) { sWl[i] = Wl[i]; sWr[i] = Wr[i]; }
    for (int i = t; i < 2048; i += 128) sWp[i] = Wedge[i];
    for (int i = t; i < 96; i += 128)   { sbl[i] = bl[i]; sbr[i] = br[i]; }
    if (t < 32) sbp[t] = bedge[t];

    int n0 = blockIdx.x * 64;
    for (int i = t; i < 4096; i += 128) {
        int r = i >> 6, c = i & 63;
        int n = n0 + r;
        sX[r * 66 + c] = (n < NN) ? x[(size_t)n * 64 + c] : 0.f;
    }
    __syncthreads();

    int er = t & 15, oc = t >> 4;
    int rb0 = er * 66, rb1 = rb0 + 16 * 66, rb2 = rb1 + 16 * 66, rb3 = rb2 + 16 * 66;

    #pragma unroll
    for (int pass = 0; pass < 2; pass++) {
        const float* W   = pass ? sWr : sWl;
        const float* bia = pass ? sbr : sbl;
        float* dst       = pass ? g_xr : g_xl;

        u64t acc[4][6];
        #pragma unroll
        for (int i = 0; i < 4; i++)
            #pragma unroll
            for (int j = 0; j < 6; j++) acc[i][j] = 0ull;

        #pragma unroll 4
        for (int k = 0; k < 64; k++) {
            u64t a0 = pk(sX[rb0 + k]), a1 = pk(sX[rb1 + k]);
            u64t a2 = pk(sX[rb2 + k]), a3 = pk(sX[rb3 + k]);
            const u64t* bp = (const u64t*)(W + k * 96 + oc * 12);
            u64t b0 = bp[0], b1 = bp[1], b2 = bp[2], b3 = bp[3], b4 = bp[4], b5 = bp[5];
            fma2(acc[0][0], a0, b0); fma2(acc[0][1], a0, b1); fma2(acc[0][2], a0, b2);
            fma2(acc[0][3], a0, b3); fma2(acc[0][4], a0, b4); fma2(acc[0][5], a0, b5);
            fma2(acc[1][0], a1, b0); fma2(acc[1][1], a1, b1); fma2(acc[1][2], a1, b2);
            fma2(acc[1][3], a1, b3); fma2(acc[1][4], a1, b4); fma2(acc[1][5], a1, b5);
            fma2(acc[2][0], a2, b0); fma2(acc[2][1], a2, b1); fma2(acc[2][2], a2, b2);
            fma2(acc[2][3], a2, b3); fma2(acc[2][4], a2, b4); fma2(acc[2][5], a2, b5);
            fma2(acc[3][0], a3, b0); fma2(acc[3][1], a3, b1); fma2(acc[3][2], a3, b2);
            fma2(acc[3][3], a3, b3); fma2(acc[3][4], a3, b4); fma2(acc[3][5], a3, b5);
        }
        #pragma unroll
        for (int i = 0; i < 4; i++) {
            int n = n0 + er + 16 * i;
            if (n < NN) {
                float o[12];
                #pragma unroll
                for (int j = 0; j < 6; j++) upk(acc[i][j], o[2 * j], o[2 * j + 1]);
                #pragma unroll
                for (int j = 0; j < 12; j++) o[j] += bia[oc * 12 + j];
                float4* op = (float4*)(dst + (size_t)n * 96 + oc * 12);
                op[0] = make_float4(o[0], o[1], o[2], o[3]);
                op[1] = make_float4(o[4], o[5], o[6], o[7]);
                op[2] = make_float4(o[8], o[9], o[10], o[11]);
            }
        }
    }

    // P pass
    {
        u64t acc[4][2];
        #pragma unroll
        for (int i = 0; i < 4; i++) { acc[i][0] = 0ull; acc[i][1] = 0ull; }
        #pragma unroll 8
        for (int k = 0; k < 64; k++) {
            u64t a0 = pk(sX[rb0 + k]), a1 = pk(sX[rb1 + k]);
            u64t a2 = pk(sX[rb2 + k]), a3 = pk(sX[rb3 + k]);
            const u64t* bp = (const u64t*)(sWp + k * 32 + oc * 4);
            u64t b0 = bp[0], b1 = bp[1];
            fma2(acc[0][0], a0, b0); fma2(acc[0][1], a0, b1);
            fma2(acc[1][0], a1, b0); fma2(acc[1][1], a1, b1);
            fma2(acc[2][0], a2, b0); fma2(acc[2][1], a2, b1);
            fma2(acc[3][0], a3, b0); fma2(acc[3][1], a3, b1);
        }
        #pragma unroll
        for (int i = 0; i < 4; i++) {
            int n = n0 + er + 16 * i;
            if (n < NN) {
                float o0, o1, o2, o3;
                upk(acc[i][0], o0, o1);
                upk(acc[i][1], o2, o3);
                *(float4*)(g_P + (size_t)n * 32 + oc * 4) = make_float4(
                    o0 + sbp[oc * 4 + 0], o1 + sbp[oc * 4 + 1],
                    o2 + sbp[oc * 4 + 2], o3 + sbp[oc * 4 + 3]);
            }
        }
    }
}

// ======================= Kernel B: fused edge kernel (128 thr, 4 rows/thread, occ=6) ========
__global__ void __launch_bounds__(128, 6) edgeK(
    const float* __restrict__ ea,
    const float* __restrict__ Wedge,
    const float* __restrict__ We, const float* __restrict__ att,
    const int* __restrict__ srcp, const int* __restrict__ dstp,
    float* __restrict__ e_out)
{
    extern __shared__ float sm[];
    float* sWb  = sm;                 // 32*32  (W_edge rows 64..95)
    float* sW2  = sWb + 1024;         // 32*96  (W_e)
    float* sEA  = sW2 + 3072;         // 64*34
    float* sE   = sEA + 64 * 34;      // 64*34
    int*   sSrc = (int*)(sE + 64 * 34); // 64
    int*   sDst = sSrc + 64;          // 64

    int t = threadIdx.x;
    for (int i = t; i < 1024; i += 128) sWb[i] = Wedge[2048 + i];
    for (int i = t; i < 3072; i += 128) sW2[i] = We[i];

    int oc = t & 7, er = t >> 3;
    int c0 = oc * 12;
    int oc4 = oc * 4;

    float attv[12];
    #pragma unroll
    for (int j = 0; j < 12; j++) attv[j] = att[c0 + j];

    int hA = c0 >> 5;
    int hB = (c0 + 11) >> 5;
    int split = (hB > hA) ? (hB * 32 - c0) : 12;

    int rb0 = er * 34, rb1 = rb0 + 16 * 34, rb2 = rb1 + 16 * 34, rb3 = rb2 + 16 * 34;

    __syncthreads();

    for (int tile = blockIdx.x; tile < EE / 64; tile += gridDim.x) {
        int e0 = tile * 64;
        if (t < 64) { sSrc[t] = srcp[e0 + t]; sDst[t] = dstp[e0 + t]; }
        for (int i = t; i < 512; i += 128) {
            int r = i >> 3, c4 = i & 7;
            float4 v = *(const float4*)(ea + (size_t)(e0 + r) * 32 + c4 * 4);
            int b = r * 34 + c4 * 4;
            sEA[b] = v.x; sEA[b + 1] = v.y; sEA[b + 2] = v.z; sEA[b + 3] = v.w;
        }
        __syncthreads();

        // early P gather, hidden under GEMM1 k-loop
        float4 pP[4];
        #pragma unroll
        for (int i = 0; i < 4; i++)
            pP[i] = *(const float4*)(g_P + (size_t)sSrc[er + 16 * i] * 32 + oc4);

        // GEMM1: tmp = ea @ Wb, e = relu(tmp + P[src])
        {
            u64t acc[4][2];
            #pragma unroll
            for (int i = 0; i < 4; i++) { acc[i][0] = 0ull; acc[i][1] = 0ull; }
            #pragma unroll 8
            for (int k = 0; k < 32; k++) {
                u64t a0 = pk(sEA[rb0 + k]), a1 = pk(sEA[rb1 + k]);
                u64t a2 = pk(sEA[rb2 + k]), a3 = pk(sEA[rb3 + k]);
                const u64t* bp = (const u64t*)(sWb + k * 32 + oc4);
                u64t b0 = bp[0], b1 = bp[1];
                fma2(acc[0][0], a0, b0); fma2(acc[0][1], a0, b1);
                fma2(acc[1][0], a1, b0); fma2(acc[1][1], a1, b1);
                fma2(acc[2][0], a2, b0); fma2(acc[2][1], a2, b1);
                fma2(acc[3][0], a3, b0); fma2(acc[3][1], a3, b1);
            }
            #pragma unroll
            for (int i = 0; i < 4; i++) {
                int row = er + 16 * i;
                float o0, o1, o2, o3;
                upk(acc[i][0], o0, o1);
                upk(acc[i][1], o2, o3);
                float v0 = fmaxf(o0 + pP[i].x, 0.f);
                float v1 = fmaxf(o1 + pP[i].y, 0.f);
                float v2 = fmaxf(o2 + pP[i].z, 0.f);
                float v3 = fmaxf(o3 + pP[i].w, 0.f);
                *(float4*)(e_out + (size_t)(e0 + row) * 32 + oc4) =
                    make_float4(v0, v1, v2, v3);
                int b = row * 34 + oc4;
                sE[b] = v0; sE[b + 1] = v1; sE[b + 2] = v2; sE[b + 3] = v3;
            }
        }
        __syncthreads();

        // GEMM2: M1 = e @ W_e, fused logits -> exp -> den atomics
        {
            u64t acc2[4][6];
            #pragma unroll
            for (int i = 0; i < 4; i++)
                #pragma unroll
                for (int j = 0; j < 6; j++) acc2[i][j] = 0ull;
            #pragma unroll 8
            for (int k = 0; k < 32; k++) {
                u64t a0 = pk(sE[rb0 + k]), a1 = pk(sE[rb1 + k]);
                u64t a2 = pk(sE[rb2 + k]), a3 = pk(sE[rb3 + k]);
                const u64t* bp = (const u64t*)(sW2 + k * 96 + c0);
                u64t b0 = bp[0], b1 = bp[1], b2 = bp[2], b3 = bp[3], b4 = bp[4], b5 = bp[5];
                fma2(acc2[0][0], a0, b0); fma2(acc2[0][1], a0, b1); fma2(acc2[0][2], a0, b2);
                fma2(acc2[0][3], a0, b3); fma2(acc2[0][4], a0, b4); fma2(acc2[0][5], a0, b5);
                fma2(acc2[1][0], a1, b0); fma2(acc2[1][1], a1, b1); fma2(acc2[1][2], a1, b2);
                fma2(acc2[1][3], a1, b3); fma2(acc2[1][4], a1, b4); fma2(acc2[1][5], a1, b5);
                fma2(acc2[2][0], a2, b0); fma2(acc2[2][1], a2, b1); fma2(acc2[2][2], a2, b2);
                fma2(acc2[2][3], a2, b3); fma2(acc2[2][4], a2, b4); fma2(acc2[2][5], a2, b5);
                fma2(acc2[3][0], a3, b0); fma2(acc2[3][1], a3, b1); fma2(acc2[3][2], a3, b2);
                fma2(acc2[3][3], a3, b3); fma2(acc2[3][4], a3, b4); fma2(acc2[3][5], a3, b5);
            }

            // pipelined epilogue: load row i+1's xl/xr while reducing row i
            float4 xa[3], xb[3], nxa[3], nxb[3];
            {
                int s0 = sSrc[er], d0 = sDst[er];
                const float4* xlp = (const float4*)(g_xl + (size_t)s0 * 96 + c0);
                const float4* xrp = (const float4*)(g_xr + (size_t)d0 * 96 + c0);
                #pragma unroll
                for (int q = 0; q < 3; q++) { xa[q] = xlp[q]; xb[q] = xrp[q]; }
            }
            #pragma unroll
            for (int i = 0; i < 4; i++) {
                int row = er + 16 * i;
                int d = sDst[row];
                if (i < 3) {
                    int s1 = sSrc[row + 16], d1 = sDst[row + 16];
                    const float4* xlp = (const float4*)(g_xl + (size_t)s1 * 96 + c0);
                    const float4* xrp = (const float4*)(g_xr + (size_t)d1 * 96 + c0);
                    #pragma unroll
                    for (int q = 0; q < 3; q++) { nxa[q] = xlp[q]; nxb[q] = xrp[q]; }
                }
                float m1v[12];
                #pragma unroll
                for (int j = 0; j < 6; j++) upk(acc2[i][j], m1v[2 * j], m1v[2 * j + 1]);
                float pA = 0.f, pB = 0.f;
                #pragma unroll
                for (int q = 0; q < 3; q++) {
                    float mm[4];
                    mm[0] = m1v[q * 4 + 0] + xa[q].x + xb[q].x;
                    mm[1] = m1v[q * 4 + 1] + xa[q].y + xb[q].y;
                    mm[2] = m1v[q * 4 + 2] + xa[q].z + xb[q].z;
                    mm[3] = m1v[q * 4 + 3] + xa[q].w + xb[q].w;
                    #pragma unroll
                    for (int jj = 0; jj < 4; jj++) {
                        int j = q * 4 + jj;
                        float m = mm[jj];
                        m = (m > 0.f) ? m : 0.2f * m;
                        float v = m * attv[j];
                        if (j < split) pA += v; else pB += v;
                    }
                }
                #pragma unroll
                for (int h = 0; h < 3; h++) {
                    float v = (hA == h ? pA : 0.f) + ((hB == h && hB != hA) ? pB : 0.f);
                    v += __shfl_xor_sync(0xffffffffu, v, 1);
                    v += __shfl_xor_sync(0xffffffffu, v, 2);
                    v += __shfl_xor_sync(0xffffffffu, v, 4);
                    if (oc == h) {
                        float ex = __expf(v);
                        g_ex[(size_t)(e0 + row) * 3 + h] = ex;
                        atomicAdd(&g_den[d * 3 + h], ex);
                    }
                }
                #pragma unroll
                for (int q = 0; q < 3; q++) { xa[q] = nxa[q]; xb[q] = nxb[q]; }
            }
        }
        __syncthreads();
    }
}

// ======================= Kernel D: scatter with fused alpha (8 edges/warp) =======================
__global__ void __launch_bounds__(256) scatterK(const int* __restrict__ srcp,
                                                const int* __restrict__ dstp)
{
    int warp = blockIdx.x * 8 + (threadIdx.x >> 5);
    int lane = threadIdx.x & 31;
    int e0 = warp * 8;

    int s_own = 0, d_own = 0;
    if (lane < 8) { s_own = srcp[e0 + lane]; d_own = dstp[e0 + lane]; }
    float a_own = 0.f;
    if (lane < 24) {
        int es = lane / 3, h = lane - es * 3;
        int d = dstp[e0 + es];
        a_own = g_ex[(size_t)(e0 + es) * 3 + h] / g_den[d * 3 + h];
    }

    #pragma unroll
    for (int i = 0; i < 6; i++) {
        int idx = lane + 32 * i;        // 0..191
        int es = idx / 24;              // 0..7
        int chunk = idx - es * 24;      // 0..23
        int h = chunk >> 3;
        int s = __shfl_sync(0xffffffffu, s_own, es);
        int d = __shfl_sync(0xffffffffu, d_own, es);
        float al = __shfl_sync(0xffffffffu, a_own, es * 3 + h);
        float4 xv = *(const float4*)(g_xl + (size_t)s * 96 + chunk * 4);
        float* gp = g_gat + (size_t)d * 96 + chunk * 4;
        asm volatile("red.global.add.v4.f32 [%0], {%1,%2,%3,%4};"
                     :: "l"(gp), "f"(al * xv.x), "f"(al * xv.y),
                        "f"(al * xv.z), "f"(al * xv.w)
                     : "memory");
    }
}

// ======================= Kernel E: node_mlp_2 — 2 threads/node, 16 outputs each ====
__global__ void __launch_bounds__(256, 5) node2K(
    const float* __restrict__ glob, const int* __restrict__ batch,
    const float* __restrict__ Wn2, const float* __restrict__ bn2,
    const float* __restrict__ bias_gat, float* __restrict__ xnew)
{
    __shared__ float sW[4096];   // 128 x 32
    __shared__ float sBg[96];
    __shared__ float sBn[32];

    int t = threadIdx.x;
    for (int i = t; i < 4096; i += 256) sW[i] = Wn2[i];
    if (t < 96) sBg[t] = bias_gat[t];
    else if (t < 128) sBn[t - 96] = bn2[t - 96];
    __syncthreads();

    int n = blockIdx.x * 128 + (t >> 1);
    int half = t & 1;                 // 0: cols 0..15, 1: cols 16..31
    bool valid = (n < NN);
    int nn = valid ? n : (NN - 1);
    int bb = batch[nn];

    u64t acc[8];
    #pragma unroll
    for (int q = 0; q < 8; q++) acc[q] = 0ull;

    const float4* gr = (const float4*)(g_gat + (size_t)nn * 96);
    const float4* gl = (const float4*)(glob + bb * 32);
    int hofs = half * 8;              // u64 offset into each W row

    // k = 0..95: gat row + bias_gat
    #pragma unroll
    for (int c4 = 0; c4 < 24; c4++) {
        float4 v = gr[c4];
        float a0 = v.x + sBg[c4 * 4 + 0];
        float a1 = v.y + sBg[c4 * 4 + 1];
        float a2 = v.z + sBg[c4 * 4 + 2];
        float a3 = v.w + sBg[c4 * 4 + 3];
        const u64t* b0 = (const u64t*)(sW + (c4 * 4 + 0) * 32) + hofs;
        const u64t* b1 = (const u64t*)(sW + (c4 * 4 + 1) * 32) + hofs;
        const u64t* b2 = (const u64t*)(sW + (c4 * 4 + 2) * 32) + hofs;
        const u64t* b3 = (const u64t*)(sW + (c4 * 4 + 3) * 32) + hofs;
        u64t p0 = pk(a0), p1 = pk(a1), p2 = pk(a2), p3 = pk(a3);
        #pragma unroll
        for (int q = 0; q < 8; q++) {
            fma2(acc[q], p0, b0[q]);
            fma2(acc[q], p1, b1[q]);
            fma2(acc[q], p2, b2[q]);
            fma2(acc[q], p3, b3[q]);
        }
    }
    // k = 96..127: glob row
    #pragma unroll
    for (int c4 = 0; c4 < 8; c4++) {
        float4 v = gl[c4];
        const u64t* b0 = (const u64t*)(sW + (96 + c4 * 4 + 0) * 32) + hofs;
        const u64t* b1 = (const u64t*)(sW + (96 + c4 * 4 + 1) * 32) + hofs;
        const u64t* b2 = (const u64t*)(sW + (96 + c4 * 4 + 2) * 32) + hofs;
        const u64t* b3 = (const u64t*)(sW + (96 + c4 * 4 + 3) * 32) + hofs;
        u64t p0 = pk(v.x), p1 = pk(v.y), p2 = pk(v.z), p3 = pk(v.w);
        #pragma unroll
        for (int q = 0; q < 8; q++) {
            fma2(acc[q], p0, b0[q]);
            fma2(acc[q], p1, b1[q]);
            fma2(acc[q], p2, b2[q]);
            fma2(acc[q], p3, b3[q]);
        }
    }

    if (valid) {
        if (half == 0) atomicAdd(&g_bcnt[bb], 1);
        float* xp = xnew + (size_t)n * 32 + half * 16;
        const float* bn = sBn + half * 16;
        #pragma unroll
        for (int q4 = 0; q4 < 4; q4++) {
            float o0, o1, o2, o3;
            upk(acc[q4 * 2], o0, o1);
            upk(acc[q4 * 2 + 1], o2, o3);
            o0 = fmaxf(o0 + bn[q4 * 4 + 0], 0.f);
            o1 = fmaxf(o1 + bn[q4 * 4 + 1], 0.f);
            o2 = fmaxf(o2 + bn[q4 * 4 + 2], 0.f);
            o3 = fmaxf(o3 + bn[q4 * 4 + 3], 0.f);
            *(float4*)(xp + q4 * 4) = make_float4(o0, o1, o2, o3);
            float* bp = g_bsum + bb * 32 + half * 16 + q4 * 4;
            asm volatile("red.global.add.v4.f32 [%0], {%1,%2,%3,%4};"
                         :: "l"(bp), "f"(o0), "f"(o1), "f"(o2), "f"(o3)
                         : "memory");
        }
    }
}

// ======================= Kernel F: global MLP =======================
__global__ void __launch_bounds__(256) globalK(
    const float* __restrict__ glob, const float* __restrict__ Wg,
    const float* __restrict__ bg, float* __restrict__ u_out)
{
    int p = blockIdx.x * 256 + threadIdx.x;
    if (p >= BBATCH * 32) return;
    int b = p >> 5, c = p & 31;
    float acc = bg[c];
    #pragma unroll
    for (int k = 0; k < 32; k++) acc += glob[b * 32 + k] * Wg[k * 32 + c];
    float cnt = fmaxf((float)g_bcnt[b], 1.f);
    float inv = 1.f / cnt;
    #pragma unroll
    for (int k = 0; k < 32; k++) acc += (g_bsum[b * 32 + k] * inv) * Wg[(32 + k) * 32 + c];
    u_out[p] = fmaxf(acc, 0.f);
}

// ======================= launch =======================
extern "C" void kernel_launch(void* const* d_in, const int* in_sizes, int n_in,
                              void* d_out, int out_size)
{
    const float* x        = (const float*)d_in[0];
    const float* ea       = (const float*)d_in[1];
    const float* glob     = (const float*)d_in[2];
    const float* W_edge   = (const float*)d_in[3];
    const float* b_edge   = (const float*)d_in[4];
    const float* W_l      = (const float*)d_in[5];
    const float* b_l      = (const float*)d_in[6];
    const float* W_r      = (const float*)d_in[7];
    const float* b_r      = (const float*)d_in[8];
    const float* W_e      = (const float*)d_in[9];
    const float* att      = (const float*)d_in[10];
    const float* bias_gat = (const float*)d_in[11];
    const float* W_n2     = (const float*)d_in[12];
    const float* b_n2     = (const float*)d_in[13];
    const float* W_g      = (const float*)d_in[14];
    const float* b_g      = (const float*)d_in[15];
    const int* eidx       = (const int*)d_in[16];
    const int* batch      = (const int*)d_in[17];
    const int* srcp = eidx;
    const int* dstp = eidx + EE;

    float* out  = (float*)d_out;
    float* o_x  = out;                       // [N,32]
    float* o_e  = out + (size_t)NN * 32;     // [E,32]
    float* o_u  = o_e + (size_t)EE * 32;     // [B,32]

    const int SMEM_A = (6144 + 6144 + 2048 + 64 * 66 + 96 + 96 + 32) * 4;   // ~75136
    const int SMEM_B = (1024 + 3072 + 64 * 34 + 64 * 34 + 128) * 4;         // ~34304

    cudaFuncSetAttribute(nodeTransformK, cudaFuncAttributeMaxDynamicSharedMemorySize, SMEM_A);
    cudaFuncSetAttribute(edgeK,          cudaFuncAttributeMaxDynamicSharedMemorySize, SMEM_B);

    void* p;
    cudaGetSymbolAddress(&p, g_den);  cudaMemsetAsync(p, 0, (size_t)NN * 3 * 4);
    cudaGetSymbolAddress(&p, g_gat);  cudaMemsetAsync(p, 0, (size_t)NN * 96 * 4);
    cudaGetSymbolAddress(&p, g_bsum); cudaMemsetAsync(p, 0, (size_t)BBATCH * 32 * 4);
    cudaGetSymbolAddress(&p, g_bcnt); cudaMemsetAsync(p, 0, (size_t)BBATCH * 4);

    nodeTransformK<<<(NN + 63) / 64, 128, SMEM_A>>>(x, W_l, b_l, W_r, b_r, W_edge, b_edge);
    edgeK<<<888, 128, SMEM_B>>>(ea, W_edge, W_e, att, srcp, dstp, o_e);
    scatterK<<<EE / 64, 256>>>(srcp, dstp);
    node2K<<<(NN + 127) / 128, 256>>>(glob, batch, W_n2, b_n2, bias_gat, o_x);
    globalK<<<(BBATCH * 32 + 255) / 256, 256>>>(glob, W_g, b_g, o_u);
}

// round 17
// speedup vs baseline: 1.3165x; 1.0194x over previous
#include <cuda_runtime.h>
#include <math.h>

#define NN 100000
#define EE 1600000
#define BBATCH 64

typedef unsigned long long u64t;

// ---------------- scratch (static device arrays; no allocation) ----------------
__device__ float    g_xl[NN * 96];      // x @ W_l + b_l
__device__ float    g_xr[NN * 96];      // x @ W_r + b_r
__device__ float    g_P [NN * 32];      // x @ W_edge[:64] + b_edge
__device__ float    g_ex[EE * 3];       // exp(logit)  (no max subtraction needed)
__device__ float    g_den[NN * 3];      // softmax denominators
__device__ float    g_gat[NN * 96];     // aggregated messages
__device__ float    g_bsum[BBATCH * 32];
__device__ int      g_bcnt[BBATCH];
__device__ int      g_tileCtr;          // edgeK work-stealing counter

// ---------------- packed f32x2 helpers ----------------
__device__ __forceinline__ void fma2(u64t& d, u64t a, u64t b) {
    asm("fma.rn.f32x2 %0, %1, %2, %0;" : "+l"(d) : "l"(a), "l"(b));
}
__device__ __forceinline__ u64t pk(float a) {
    u64t r;
    asm("mov.b64 %0, {%1, %1};" : "=l"(r) : "f"(a));
    return r;
}
__device__ __forceinline__ void upk(u64t v, float& lo, float& hi) {
    asm("mov.b64 {%0, %1}, %2;" : "=f"(lo), "=f"(hi) : "l"(v));
}

// ======================= Kernel A: node transforms xl, xr, P (staged weights) =======
__global__ void __launch_bounds__(128) nodeTransformK(
    const float* __restrict__ x,
    const float* __restrict__ Wl, const float* __restrict__ bl,
    const float* __restrict__ Wr, const float* __restrict__ br,
    const float* __restrict__ Wedge, const float* __restrict__ bedge)
{
    extern __shared__ float sm[];
    float* sW  = sm;               // 64*96 (Wl, then Wr)
    float* sWp = sW + 6144;        // 64*32
    float* sX  = sWp + 2048;       // 64*66
    float* sbl = sX + 64 * 66;     // 96
    float* sbr = sbl + 96;         // 96
    float* sbp = sbr + 96;         // 32

    int t = threadIdx.x;
    for (int i = t; i < 6144; i += 128) sW[i] = Wl[i];
    for (int i = t; i < 2048; i += 128) sWp[i] = Wedge[i];
    for (int i = t; i < 96; i += 128)   { sbl[i] = bl[i]; sbr[i] = br[i]; }
    if (t < 32) sbp[t] = bedge[t];

    int n0 = blockIdx.x * 64;
    for (int i = t; i < 4096; i += 128) {
        int r = i >> 6, c = i & 63;
        int n = n0 + r;
        sX[r * 66 + c] = (n < NN) ? x[(size_t)n * 64 + c] : 0.f;
    }
    __syncthreads();

    int er = t & 15, oc = t >> 4;
    int rb0 = er * 66, rb1 = rb0 + 16 * 66, rb2 = rb1 + 16 * 66, rb3 = rb2 + 16 * 66;

    // ---- pass 0: xl (sW holds Wl) ----
    {
        u64t acc[4][6];
        #pragma unroll
        for (int i = 0; i < 4; i++)
            #pragma unroll
            for (int j = 0; j < 6; j++) acc[i][j] = 0ull;

        #pragma unroll 4
        for (int k = 0; k < 64; k++) {
            u64t a0 = pk(sX[rb0 + k]), a1 = pk(sX[rb1 + k]);
            u64t a2 = pk(sX[rb2 + k]), a3 = pk(sX[rb3 + k]);
            const u64t* bp = (const u64t*)(sW + k * 96 + oc * 12);
            u64t b0 = bp[0], b1 = bp[1], b2 = bp[2], b3 = bp[3], b4 = bp[4], b5 = bp[5];
            fma2(acc[0][0], a0, b0); fma2(acc[0][1], a0, b1); fma2(acc[0][2], a0, b2);
            fma2(acc[0][3], a0, b3); fma2(acc[0][4], a0, b4); fma2(acc[0][5], a0, b5);
            fma2(acc[1][0], a1, b0); fma2(acc[1][1], a1, b1); fma2(acc[1][2], a1, b2);
            fma2(acc[1][3], a1, b3); fma2(acc[1][4], a1, b4); fma2(acc[1][5], a1, b5);
            fma2(acc[2][0], a2, b0); fma2(acc[2][1], a2, b1); fma2(acc[2][2], a2, b2);
            fma2(acc[2][3], a2, b3); fma2(acc[2][4], a2, b4); fma2(acc[2][5], a2, b5);
            fma2(acc[3][0], a3, b0); fma2(acc[3][1], a3, b1); fma2(acc[3][2], a3, b2);
            fma2(acc[3][3], a3, b3); fma2(acc[3][4], a3, b4); fma2(acc[3][5], a3, b5);
        }
        #pragma unroll
        for (int i = 0; i < 4; i++) {
            int n = n0 + er + 16 * i;
            if (n < NN) {
                float o[12];
                #pragma unroll
                for (int j = 0; j < 6; j++) upk(acc[i][j], o[2 * j], o[2 * j + 1]);
                #pragma unroll
                for (int j = 0; j < 12; j++) o[j] += sbl[oc * 12 + j];
                float4* op = (float4*)(g_xl + (size_t)n * 96 + oc * 12);
                op[0] = make_float4(o[0], o[1], o[2], o[3]);
                op[1] = make_float4(o[4], o[5], o[6], o[7]);
                op[2] = make_float4(o[8], o[9], o[10], o[11]);
            }
        }
    }

    // ---- P pass (independent of sW) ----
    {
        u64t acc[4][2];
        #pragma unroll
        for (int i = 0; i < 4; i++) { acc[i][0] = 0ull; acc[i][1] = 0ull; }
        #pragma unroll 8
        for (int k = 0; k < 64; k++) {
            u64t a0 = pk(sX[rb0 + k]), a1 = pk(sX[rb1 + k]);
            u64t a2 = pk(sX[rb2 + k]), a3 = pk(sX[rb3 + k]);
            const u64t* bp = (const u64t*)(sWp + k * 32 + oc * 4);
            u64t b0 = bp[0], b1 = bp[1];
            fma2(acc[0][0], a0, b0); fma2(acc[0][1], a0, b1);
            fma2(acc[1][0], a1, b0); fma2(acc[1][1], a1, b1);
            fma2(acc[2][0], a2, b0); fma2(acc[2][1], a2, b1);
            fma2(acc[3][0], a3, b0); fma2(acc[3][1], a3, b1);
        }
        #pragma unroll
        for (int i = 0; i < 4; i++) {
            int n = n0 + er + 16 * i;
            if (n < NN) {
                float o0, o1, o2, o3;
                upk(acc[i][0], o0, o1);
                upk(acc[i][1], o2, o3);
                *(float4*)(g_P + (size_t)n * 32 + oc * 4) = make_float4(
                    o0 + sbp[oc * 4 + 0], o1 + sbp[oc * 4 + 1],
                    o2 + sbp[oc * 4 + 2], o3 + sbp[oc * 4 + 3]);
            }
        }
    }

    // ---- reload sW with Wr, then pass 1: xr ----
    __syncthreads();
    for (int i = t; i < 6144; i += 128) sW[i] = Wr[i];
    __syncthreads();

    {
        u64t acc[4][6];
        #pragma unroll
        for (int i = 0; i < 4; i++)
            #pragma unroll
            for (int j = 0; j < 6; j++) acc[i][j] = 0ull;

        #pragma unroll 4
        for (int k = 0; k < 64; k++) {
            u64t a0 = pk(sX[rb0 + k]), a1 = pk(sX[rb1 + k]);
            u64t a2 = pk(sX[rb2 + k]), a3 = pk(sX[rb3 + k]);
            const u64t* bp = (const u64t*)(sW + k * 96 + oc * 12);
            u64t b0 = bp[0], b1 = bp[1], b2 = bp[2], b3 = bp[3], b4 = bp[4], b5 = bp[5];
            fma2(acc[0][0], a0, b0); fma2(acc[0][1], a0, b1); fma2(acc[0][2], a0, b2);
            fma2(acc[0][3], a0, b3); fma2(acc[0][4], a0, b4); fma2(acc[0][5], a0, b5);
            fma2(acc[1][0], a1, b0); fma2(acc[1][1], a1, b1); fma2(acc[1][2], a1, b2);
            fma2(acc[1][3], a1, b3); fma2(acc[1][4], a1, b4); fma2(acc[1][5], a1, b5);
            fma2(acc[2][0], a2, b0); fma2(acc[2][1], a2, b1); fma2(acc[2][2], a2, b2);
            fma2(acc[2][3], a2, b3); fma2(acc[2][4], a2, b4); fma2(acc[2][5], a2, b5);
            fma2(acc[3][0], a3, b0); fma2(acc[3][1], a3, b1); fma2(acc[3][2], a3, b2);
            fma2(acc[3][3], a3, b3); fma2(acc[3][4], a3, b4); fma2(acc[3][5], a3, b5);
        }
        #pragma unroll
        for (int i = 0; i < 4; i++) {
            int n = n0 + er + 16 * i;
            if (n < NN) {
                float o[12];
                #pragma unroll
                for (int j = 0; j < 6; j++) upk(acc[i][j], o[2 * j], o[2 * j + 1]);
                #pragma unroll
                for (int j = 0; j < 12; j++) o[j] += sbr[oc * 12 + j];
                float4* op = (float4*)(g_xr + (size_t)n * 96 + oc * 12);
                op[0] = make_float4(o[0], o[1], o[2], o[3]);
                op[1] = make_float4(o[4], o[5], o[6], o[7]);
                op[2] = make_float4(o[8], o[9], o[10], o[11]);
            }
        }
    }
}

// ======================= Kernel B: fused edge kernel (128 thr, occ=6, work-stealing) ========
__global__ void __launch_bounds__(128, 6) edgeK(
    const float* __restrict__ ea,
    const float* __restrict__ Wedge,
    const float* __restrict__ We, const float* __restrict__ att,
    const int* __restrict__ srcp, const int* __restrict__ dstp,
    float* __restrict__ e_out)
{
    extern __shared__ float sm[];
    float* sWb  = sm;                 // 32*32  (W_edge rows 64..95)
    float* sW2  = sWb + 1024;         // 32*96  (W_e)
    float* sEA  = sW2 + 3072;         // 64*34
    float* sE   = sEA + 64 * 34;      // 64*34
    int*   sSrc = (int*)(sE + 64 * 34); // 64
    int*   sDst = sSrc + 64;          // 64
    int*   sNext = sDst + 64;         // 1

    int t = threadIdx.x;
    for (int i = t; i < 1024; i += 128) sWb[i] = Wedge[2048 + i];
    for (int i = t; i < 3072; i += 128) sW2[i] = We[i];

    int oc = t & 7, er = t >> 3;
    int c0 = oc * 12;
    int oc4 = oc * 4;

    float attv[12];
    #pragma unroll
    for (int j = 0; j < 12; j++) attv[j] = att[c0 + j];

    int hA = c0 >> 5;
    int hB = (c0 + 11) >> 5;
    int split = (hB > hA) ? (hB * 32 - c0) : 12;

    int rb0 = er * 34, rb1 = rb0 + 16 * 34, rb2 = rb1 + 16 * 34, rb3 = rb2 + 16 * 34;

    const int nTiles = EE / 64;
    if (t == 0) sNext[0] = atomicAdd(&g_tileCtr, 1);
    __syncthreads();
    int tile = sNext[0];

    while (tile < nTiles) {
        int e0 = tile * 64;
        if (t < 64) { sSrc[t] = srcp[e0 + t]; sDst[t] = dstp[e0 + t]; }
        for (int i = t; i < 512; i += 128) {
            int r = i >> 3, c4 = i & 7;
            float4 v = *(const float4*)(ea + (size_t)(e0 + r) * 32 + c4 * 4);
            int b = r * 34 + c4 * 4;
            sEA[b] = v.x; sEA[b + 1] = v.y; sEA[b + 2] = v.z; sEA[b + 3] = v.w;
        }
        __syncthreads();

        // early P gather, hidden under GEMM1 k-loop
        float4 pP[4];
        #pragma unroll
        for (int i = 0; i < 4; i++)
            pP[i] = *(const float4*)(g_P + (size_t)sSrc[er + 16 * i] * 32 + oc4);

        // GEMM1: tmp = ea @ Wb, e = relu(tmp + P[src])
        {
            u64t acc[4][2];
            #pragma unroll
            for (int i = 0; i < 4; i++) { acc[i][0] = 0ull; acc[i][1] = 0ull; }
            #pragma unroll 8
            for (int k = 0; k < 32; k++) {
                u64t a0 = pk(sEA[rb0 + k]), a1 = pk(sEA[rb1 + k]);
                u64t a2 = pk(sEA[rb2 + k]), a3 = pk(sEA[rb3 + k]);
                const u64t* bp = (const u64t*)(sWb + k * 32 + oc4);
                u64t b0 = bp[0], b1 = bp[1];
                fma2(acc[0][0], a0, b0); fma2(acc[0][1], a0, b1);
                fma2(acc[1][0], a1, b0); fma2(acc[1][1], a1, b1);
                fma2(acc[2][0], a2, b0); fma2(acc[2][1], a2, b1);
                fma2(acc[3][0], a3, b0); fma2(acc[3][1], a3, b1);
            }
            #pragma unroll
            for (int i = 0; i < 4; i++) {
                int row = er + 16 * i;
                float o0, o1, o2, o3;
                upk(acc[i][0], o0, o1);
                upk(acc[i][1], o2, o3);
                float v0 = fmaxf(o0 + pP[i].x, 0.f);
                float v1 = fmaxf(o1 + pP[i].y, 0.f);
                float v2 = fmaxf(o2 + pP[i].z, 0.f);
                float v3 = fmaxf(o3 + pP[i].w, 0.f);
                *(float4*)(e_out + (size_t)(e0 + row) * 32 + oc4) =
                    make_float4(v0, v1, v2, v3);
                int b = row * 34 + oc4;
                sE[b] = v0; sE[b + 1] = v1; sE[b + 2] = v2; sE[b + 3] = v3;
            }
        }
        __syncthreads();

        // GEMM2: M1 = e @ W_e, fused logits -> exp -> den atomics
        {
            u64t acc2[4][6];
            #pragma unroll
            for (int i = 0; i < 4; i++)
                #pragma unroll
                for (int j = 0; j < 6; j++) acc2[i][j] = 0ull;
            #pragma unroll 8
            for (int k = 0; k < 32; k++) {
                u64t a0 = pk(sE[rb0 + k]), a1 = pk(sE[rb1 + k]);
                u64t a2 = pk(sE[rb2 + k]), a3 = pk(sE[rb3 + k]);
                const u64t* bp = (const u64t*)(sW2 + k * 96 + c0);
                u64t b0 = bp[0], b1 = bp[1], b2 = bp[2], b3 = bp[3], b4 = bp[4], b5 = bp[5];
                fma2(acc2[0][0], a0, b0); fma2(acc2[0][1], a0, b1); fma2(acc2[0][2], a0, b2);
                fma2(acc2[0][3], a0, b3); fma2(acc2[0][4], a0, b4); fma2(acc2[0][5], a0, b5);
                fma2(acc2[1][0], a1, b0); fma2(acc2[1][1], a1, b1); fma2(acc2[1][2], a1, b2);
                fma2(acc2[1][3], a1, b3); fma2(acc2[1][4], a1, b4); fma2(acc2[1][5], a1, b5);
                fma2(acc2[2][0], a2, b0); fma2(acc2[2][1], a2, b1); fma2(acc2[2][2], a2, b2);
                fma2(acc2[2][3], a2, b3); fma2(acc2[2][4], a2, b4); fma2(acc2[2][5], a2, b5);
                fma2(acc2[3][0], a3, b0); fma2(acc2[3][1], a3, b1); fma2(acc2[3][2], a3, b2);
                fma2(acc2[3][3], a3, b3); fma2(acc2[3][4], a3, b4); fma2(acc2[3][5], a3, b5);
            }

            // pipelined epilogue: load row i+1's xl/xr while reducing row i
            float4 xa[3], xb[3], nxa[3], nxb[3];
            {
                int s0 = sSrc[er], d0 = sDst[er];
                const float4* xlp = (const float4*)(g_xl + (size_t)s0 * 96 + c0);
                const float4* xrp = (const float4*)(g_xr + (size_t)d0 * 96 + c0);
                #pragma unroll
                for (int q = 0; q < 3; q++) { xa[q] = xlp[q]; xb[q] = xrp[q]; }
            }
            #pragma unroll
            for (int i = 0; i < 4; i++) {
                int row = er + 16 * i;
                int d = sDst[row];
                if (i < 3) {
                    int s1 = sSrc[row + 16], d1 = sDst[row + 16];
                    const float4* xlp = (const float4*)(g_xl + (size_t)s1 * 96 + c0);
                    const float4* xrp = (const float4*)(g_xr + (size_t)d1 * 96 + c0);
                    #pragma unroll
                    for (int q = 0; q < 3; q++) { nxa[q] = xlp[q]; nxb[q] = xrp[q]; }
                }
                float m1v[12];
                #pragma unroll
                for (int j = 0; j < 6; j++) upk(acc2[i][j], m1v[2 * j], m1v[2 * j + 1]);
                float pA = 0.f, pB = 0.f;
                #pragma unroll
                for (int q = 0; q < 3; q++) {
                    float mm[4];
                    mm[0] = m1v[q * 4 + 0] + xa[q].x + xb[q].x;
                    mm[1] = m1v[q * 4 + 1] + xa[q].y + xb[q].y;
                    mm[2] = m1v[q * 4 + 2] + xa[q].z + xb[q].z;
                    mm[3] = m1v[q * 4 + 3] + xa[q].w + xb[q].w;
                    #pragma unroll
                    for (int jj = 0; jj < 4; jj++) {
                        int j = q * 4 + jj;
                        float m = mm[jj];
                        m = (m > 0.f) ? m : 0.2f * m;
                        float v = m * attv[j];
                        if (j < split) pA += v; else pB += v;
                    }
                }
                #pragma unroll
                for (int h = 0; h < 3; h++) {
                    float v = (hA == h ? pA : 0.f) + ((hB == h && hB != hA) ? pB : 0.f);
                    v += __shfl_xor_sync(0xffffffffu, v, 1);
                    v += __shfl_xor_sync(0xffffffffu, v, 2);
                    v += __shfl_xor_sync(0xffffffffu, v, 4);
                    if (oc == h) {
                        float ex = __expf(v);
                        g_ex[(size_t)(e0 + row) * 3 + h] = ex;
                        atomicAdd(&g_den[d * 3 + h], ex);
                    }
                }
                #pragma unroll
                for (int q = 0; q < 3; q++) { xa[q] = nxa[q]; xb[q] = nxb[q]; }
            }
        }

        if (t == 0) sNext[0] = atomicAdd(&g_tileCtr, 1);
        __syncthreads();
        tile = sNext[0];
    }
}

// ======================= Kernel D: scatter with fused alpha (8 edges/warp) =======================
__global__ void __launch_bounds__(256) scatterK(const int* __restrict__ srcp,
                                                const int* __restrict__ dstp)
{
    int warp = blockIdx.x * 8 + (threadIdx.x >> 5);
    int lane = threadIdx.x & 31;
    int e0 = warp * 8;

    int s_own = 0, d_own = 0;
    if (lane < 8) { s_own = srcp[e0 + lane]; d_own = dstp[e0 + lane]; }
    float a_own = 0.f;
    if (lane < 24) {
        int es = lane / 3, h = lane - es * 3;
        int d = dstp[e0 + es];
        a_own = g_ex[(size_t)(e0 + es) * 3 + h] / g_den[d * 3 + h];
    }

    #pragma unroll
    for (int i = 0; i < 6; i++) {
        int idx = lane + 32 * i;        // 0..191
        int es = idx / 24;              // 0..7
        int chunk = idx - es * 24;      // 0..23
        int h = chunk >> 3;
        int s = __shfl_sync(0xffffffffu, s_own, es);
        int d = __shfl_sync(0xffffffffu, d_own, es);
        float al = __shfl_sync(0xffffffffu, a_own, es * 3 + h);
        float4 xv = *(const float4*)(g_xl + (size_t)s * 96 + chunk * 4);
        float* gp = g_gat + (size_t)d * 96 + chunk * 4;
        asm volatile("red.global.add.v4.f32 [%0], {%1,%2,%3,%4};"
                     :: "l"(gp), "f"(al * xv.x), "f"(al * xv.y),
                        "f"(al * xv.z), "f"(al * xv.w)
                     : "memory");
    }
}

// ======================= Kernel E: node_mlp_2 — 2 threads/node, 16 outputs each ====
__global__ void __launch_bounds__(256, 5) node2K(
    const float* __restrict__ glob, const int* __restrict__ batch,
    const float* __restrict__ Wn2, const float* __restrict__ bn2,
    const float* __restrict__ bias_gat, float* __restrict__ xnew)
{
    __shared__ float sW[4096];   // 128 x 32
    __shared__ float sBg[96];
    __shared__ float sBn[32];

    int t = threadIdx.x;
    for (int i = t; i < 4096; i += 256) sW[i] = Wn2[i];
    if (t < 96) sBg[t] = bias_gat[t];
    else if (t < 128) sBn[t - 96] = bn2[t - 96];
    __syncthreads();

    int n = blockIdx.x * 128 + (t >> 1);
    int half = t & 1;                 // 0: cols 0..15, 1: cols 16..31
    bool valid = (n < NN);
    int nn = valid ? n : (NN - 1);
    int bb = batch[nn];

    u64t acc[8];
    #pragma unroll
    for (int q = 0; q < 8; q++) acc[q] = 0ull;

    const float4* gr = (const float4*)(g_gat + (size_t)nn * 96);
    const float4* gl = (const float4*)(glob + bb * 32);
    int hofs = half * 8;              // u64 offset into each W row

    // k = 0..95: gat row + bias_gat
    #pragma unroll
    for (int c4 = 0; c4 < 24; c4++) {
        float4 v = gr[c4];
        float a0 = v.x + sBg[c4 * 4 + 0];
        float a1 = v.y + sBg[c4 * 4 + 1];
        float a2 = v.z + sBg[c4 * 4 + 2];
        float a3 = v.w + sBg[c4 * 4 + 3];
        const u64t* b0 = (const u64t*)(sW + (c4 * 4 + 0) * 32) + hofs;
        const u64t* b1 = (const u64t*)(sW + (c4 * 4 + 1) * 32) + hofs;
        const u64t* b2 = (const u64t*)(sW + (c4 * 4 + 2) * 32) + hofs;
        const u64t* b3 = (const u64t*)(sW + (c4 * 4 + 3) * 32) + hofs;
        u64t p0 = pk(a0), p1 = pk(a1), p2 = pk(a2), p3 = pk(a3);
        #pragma unroll
        for (int q = 0; q < 8; q++) {
            fma2(acc[q], p0, b0[q]);
            fma2(acc[q], p1, b1[q]);
            fma2(acc[q], p2, b2[q]);
            fma2(acc[q], p3, b3[q]);
        }
    }
    // k = 96..127: glob row
    #pragma unroll
    for (int c4 = 0; c4 < 8; c4++) {
        float4 v = gl[c4];
        const u64t* b0 = (const u64t*)(sW + (96 + c4 * 4 + 0) * 32) + hofs;
        const u64t* b1 = (const u64t*)(sW + (96 + c4 * 4 + 1) * 32) + hofs;
        const u64t* b2 = (const u64t*)(sW + (96 + c4 * 4 + 2) * 32) + hofs;
        const u64t* b3 = (const u64t*)(sW + (96 + c4 * 4 + 3) * 32) + hofs;
        u64t p0 = pk(v.x), p1 = pk(v.y), p2 = pk(v.z), p3 = pk(v.w);
        #pragma unroll
        for (int q = 0; q < 8; q++) {
            fma2(acc[q], p0, b0[q]);
            fma2(acc[q], p1, b1[q]);
            fma2(acc[q], p2, b2[q]);
            fma2(acc[q], p3, b3[q]);
        }
    }

    if (valid) {
        if (half == 0) atomicAdd(&g_bcnt[bb], 1);
        float* xp = xnew + (size_t)n * 32 + half * 16;
        const float* bn = sBn + half * 16;
        #pragma unroll
        for (int q4 = 0; q4 < 4; q4++) {
            float o0, o1, o2, o3;
            upk(acc[q4 * 2], o0, o1);
            upk(acc[q4 * 2 + 1], o2, o3);
            o0 = fmaxf(o0 + bn[q4 * 4 + 0], 0.f);
            o1 = fmaxf(o1 + bn[q4 * 4 + 1], 0.f);
            o2 = fmaxf(o2 + bn[q4 * 4 + 2], 0.f);
            o3 = fmaxf(o3 + bn[q4 * 4 + 3], 0.f);
            *(float4*)(xp + q4 * 4) = make_float4(o0, o1, o2, o3);
            float* bp = g_bsum + bb * 32 + half * 16 + q4 * 4;
            asm volatile("red.global.add.v4.f32 [%0], {%1,%2,%3,%4};"
                         :: "l"(bp), "f"(o0), "f"(o1), "f"(o2), "f"(o3)
                         : "memory");
        }
    }
}

// ======================= Kernel F: global MLP =======================
__global__ void __launch_bounds__(256) globalK(
    const float* __restrict__ glob, const float* __restrict__ Wg,
    const float* __restrict__ bg, float* __restrict__ u_out)
{
    int p = blockIdx.x * 256 + threadIdx.x;
    if (p >= BBATCH * 32) return;
    int b = p >> 5, c = p & 31;
    float acc = bg[c];
    #pragma unroll
    for (int k = 0; k < 32; k++) acc += glob[b * 32 + k] * Wg[k * 32 + c];
    float cnt = fmaxf((float)g_bcnt[b], 1.f);
    float inv = 1.f / cnt;
    #pragma unroll
    for (int k = 0; k < 32; k++) acc += (g_bsum[b * 32 + k] * inv) * Wg[(32 + k) * 32 + c];
    u_out[p] = fmaxf(acc, 0.f);
}

// ======================= launch =======================
extern "C" void kernel_launch(void* const* d_in, const int* in_sizes, int n_in,
                              void* d_out, int out_size)
{
    const float* x        = (const float*)d_in[0];
    const float* ea       = (const float*)d_in[1];
    const float* glob     = (const float*)d_in[2];
    const float* W_edge   = (const float*)d_in[3];
    const float* b_edge   = (const float*)d_in[4];
    const float* W_l      = (const float*)d_in[5];
    const float* b_l      = (const float*)d_in[6];
    const float* W_r      = (const float*)d_in[7];
    const float* b_r      = (const float*)d_in[8];
    const float* W_e      = (const float*)d_in[9];
    const float* att      = (const float*)d_in[10];
    const float* bias_gat = (const float*)d_in[11];
    const float* W_n2     = (const float*)d_in[12];
    const float* b_n2     = (const float*)d_in[13];
    const float* W_g      = (const float*)d_in[14];
    const float* b_g      = (const float*)d_in[15];
    const int* eidx       = (const int*)d_in[16];
    const int* batch      = (const int*)d_in[17];
    const int* srcp = eidx;
    const int* dstp = eidx + EE;

    float* out  = (float*)d_out;
    float* o_x  = out;                       // [N,32]
    float* o_e  = out + (size_t)NN * 32;     // [E,32]
    float* o_u  = o_e + (size_t)EE * 32;     // [B,32]

    const int SMEM_A = (6144 + 2048 + 64 * 66 + 96 + 96 + 32) * 4;          // ~50560
    const int SMEM_B = (1024 + 3072 + 64 * 34 + 64 * 34 + 132) * 4;         // ~34320

    cudaFuncSetAttribute(nodeTransformK, cudaFuncAttributeMaxDynamicSharedMemorySize, SMEM_A);
    cudaFuncSetAttribute(edgeK,          cudaFuncAttributeMaxDynamicSharedMemorySize, SMEM_B);

    void* p;
    cudaGetSymbolAddress(&p, g_den);     cudaMemsetAsync(p, 0, (size_t)NN * 3 * 4);
    cudaGetSymbolAddress(&p, g_gat);     cudaMemsetAsync(p, 0, (size_t)NN * 96 * 4);
    cudaGetSymbolAddress(&p, g_bsum);    cudaMemsetAsync(p, 0, (size_t)BBATCH * 32 * 4);
    cudaGetSymbolAddress(&p, g_bcnt);    cudaMemsetAsync(p, 0, (size_t)BBATCH * 4);
    cudaGetSymbolAddress(&p, g_tileCtr); cudaMemsetAsync(p, 0, 4);

    nodeTransformK<<<(NN + 63) / 64, 128, SMEM_A>>>(x, W_l, b_l, W_r, b_r, W_edge, b_edge);
    edgeK<<<888, 128, SMEM_B>>>(ea, W_edge, W_e, att, srcp, dstp, o_e);
    scatterK<<<EE / 64, 256>>>(srcp, dstp);
    node2K<<<(NN + 127) / 128, 256>>>(glob, batch, W_n2, b_n2, bias_gat, o_x);
    globalK<<<(BBATCH * 32 + 255) / 256, 256>>>(glob, W_g, b_g, o_u);
}